// round 1
// baseline (speedup 1.0000x reference)
#include <cuda_runtime.h>
#include <cuda_bf16.h>

// ---------------------------------------------------------------------------
// SphericalHarmonicTransform, L=10, N=2e6 points -> 121 reduced coefficients.
//
// Reference identity exploited: z2 = (x/2,-y/2) = -conj(z1), z1 = (-x/2,-y/2)
//   zreal(p,q) = z1r[p]^2 - z1i[q]^2
//   zimag(p,q) = (-1)^q * (z1i[p]*z1r[q] - z1r[p]*z1i[q])
// All combinatorial constants folded into compile-time immediates.
// ---------------------------------------------------------------------------

#define NBLK  296
#define NTHR  256
#define NWARP ((NBLK * NTHR) / 32)   // 2368 warps total

__device__ float g_part[121 * NWARP];   // per-warp partial sums, [j][warp]

// ----- compile-time math -----
__host__ __device__ constexpr double cfact(int n) {
    double r = 1.0;
    for (int i = 2; i <= n; ++i) r *= (double)i;
    return r;
}
__host__ __device__ constexpr double csqrt(double x) {
    if (x <= 0.0) return 0.0;
    double g = (x > 1.0) ? x : 1.0;
    for (int i = 0; i < 200; ++i) g = 0.5 * (g + x / g);
    return g;
}
// coeff = 1/(p! q! s!) * sqrt((l+m)!(l-m)!) * sqrt((2l+1)/(4pi)) * f(m)
// with f(m) = 1 (m==0) else sqrt(2)*(-1)^m.  (The extra (-1)^q for the
// imaginary path is applied at the use site.)
__host__ __device__ constexpr float coefR(int l, int p, int q) {
    const int m = p - q;
    const int s = l - p - q;
    double c  = 1.0 / (cfact(p) * cfact(q) * cfact(s));
    double sc = csqrt(cfact(l + m) * cfact(l - m)) *
                csqrt((2.0 * l + 1.0) / (4.0 * 3.14159265358979323846264338327950288));
    double f  = (m == 0) ? 1.0 : (csqrt(2.0) * ((m & 1) ? -1.0 : 1.0));
    return (float)(c * sc * f);
}

// ----- compile-time for: indices are constexpr inside the functor -----
template <int N> struct IntC { static constexpr int value = N; };

template <int Start, int End, class F>
__device__ __forceinline__ void static_for(F&& f) {
    if constexpr (Start < End) {
        f(IntC<Start>{});
        static_for<Start + 1, End>(static_cast<F&&>(f));
    }
}

// ---------------------------------------------------------------------------
__global__ __launch_bounds__(NTHR, 1)
void sht_main_kernel(const float* __restrict__ pos, int npts) {
    float acc[121];
#pragma unroll
    for (int j = 0; j < 121; ++j) acc[j] = 0.0f;

    const int stride = gridDim.x * blockDim.x;
    for (int i = blockIdx.x * blockDim.x + threadIdx.x; i < npts; i += stride) {
        const float x  = pos[3 * i + 0];
        const float y  = pos[3 * i + 1];
        const float z0 = pos[3 * i + 2];

        const float r2 = fmaf(x, x, fmaf(y, y, z0 * z0));
        const float r  = sqrtf(r2);

        // w[l] = mask * x0 * r^l
        float w[11];
        w[0] = (r2 > 0.0f) ? z0 : 0.0f;
#pragma unroll
        for (int l = 1; l < 11; ++l) w[l] = w[l - 1] * r;

        // z1^p powers, z1 = (-x/2, -y/2), via repeated complex multiply
        float zr[11], zi[11];
        zr[0] = 1.0f; zi[0] = 0.0f;
        const float ar = -0.5f * x;
        const float ai = -0.5f * y;
#pragma unroll
        for (int p = 1; p < 11; ++p) {
            zr[p] = fmaf(ar, zr[p - 1], -(ai * zi[p - 1]));
            zi[p] = fmaf(ar, zi[p - 1],  (ai * zr[p - 1]));
        }
        float sr[11], si[11];
#pragma unroll
        for (int p = 0; p < 11; ++p) { sr[p] = zr[p] * zr[p]; si[p] = zi[p] * zi[p]; }

        // pair-major accumulation: 66 (p,q) pairs, l = p+q..10
        static_for<0, 11>([&](auto pc) {
            constexpr int p = decltype(pc)::value;
            static_for<0, p + 1>([&](auto qc) {
                constexpr int q = decltype(qc)::value;
                if constexpr (p + q <= 10) {
                    constexpr int m = p - q;
                    const float D  = sr[p] - si[q];                      // zreal
                    const float Pv = zi[p] * zr[q] - zr[p] * zi[q];      // +/- zimag
                    static_for<p + q, 11>([&](auto lc) {
                        constexpr int l  = decltype(lc)::value;
                        constexpr float cR = coefR(l, p, q);
                        const float t = cR * w[l];                       // FMUL-imm
                        acc[l * l + l + m] = fmaf(D, t, acc[l * l + l + m]);
                        if constexpr (m > 0) {
                            if constexpr (q & 1)
                                acc[l * l + l - m] = fmaf(Pv, -t, acc[l * l + l - m]);
                            else
                                acc[l * l + l - m] = fmaf(Pv,  t, acc[l * l + l - m]);
                        }
                    });
                }
            });
        });
    }

    // warp-level tree reduce, lane 0 stores per-warp partials
    const int lane = threadIdx.x & 31;
    const int gw   = (blockIdx.x * blockDim.x + threadIdx.x) >> 5;
#pragma unroll
    for (int j = 0; j < 121; ++j) {
        float v = acc[j];
#pragma unroll
        for (int o = 16; o > 0; o >>= 1) v += __shfl_xor_sync(0xffffffffu, v, o);
        if (lane == 0) g_part[j * NWARP + gw] = v;
    }
}

// ---------------------------------------------------------------------------
__global__ void sht_reduce_kernel(float* __restrict__ out) {
    const int j = blockIdx.x;      // 0..120
    double s = 0.0;
    for (int t = threadIdx.x; t < NWARP; t += blockDim.x)
        s += (double)g_part[j * NWARP + t];
    __shared__ double sh[256];
    sh[threadIdx.x] = s;
    __syncthreads();
    for (int k = 128; k > 0; k >>= 1) {
        if (threadIdx.x < k) sh[threadIdx.x] += sh[threadIdx.x + k];
        __syncthreads();
    }
    if (threadIdx.x == 0) out[j] = (float)sh[0];
}

// ---------------------------------------------------------------------------
extern "C" void kernel_launch(void* const* d_in, const int* in_sizes, int n_in,
                              void* d_out, int out_size) {
    const float* pos = (const float*)d_in[0];
    const int npts = in_sizes[0] / 3;
    sht_main_kernel<<<NBLK, NTHR>>>(pos, npts);
    sht_reduce_kernel<<<121, 256>>>((float*)d_out);
}

// round 2
// speedup vs baseline: 1.0303x; 1.0303x over previous
#include <cuda_runtime.h>
#include <cuda_bf16.h>

// ---------------------------------------------------------------------------
// SphericalHarmonicTransform, L=10, N=2e6 points -> 121 coefficients.
//
// Refactor vs R1:
//   cR(l,p,q) = A(l,m) * B(p,q) * 1/s!,   s = l-(p+q)
//   term = D * w[k] * B * h[s],  h[s] = r^s/s!,  A applied in epilogue.
//   Real/imag channels of each m>0 pair packed into one fma.rn.f32x2.
// ---------------------------------------------------------------------------

#define NBLK 304
#define NTHR 256

__device__ float g_part[121 * NBLK];   // per-block partials, [j][block]

// ----- compile-time math -----
__host__ __device__ constexpr double cfact(int n) {
    double r = 1.0;
    for (int i = 2; i <= n; ++i) r *= (double)i;
    return r;
}
// B(p,q) = 1/(p! q!)
__host__ __device__ constexpr float cB(int p, int q) {
    return (float)(1.0 / (cfact(p) * cfact(q)));
}

// ----- compile-time for -----
template <int N> struct IntC { static constexpr int value = N; };
template <int Start, int End, class F>
__device__ __forceinline__ void static_for(F&& f) {
    if constexpr (Start < End) {
        f(IntC<Start>{});
        static_for<Start + 1, End>(static_cast<F&&>(f));
    }
}

// ----- packed f32x2 helpers -----
__device__ __forceinline__ unsigned long long pack2(float lo, float hi) {
    unsigned long long r;
    asm("mov.b64 %0, {%1, %2};" : "=l"(r) : "f"(lo), "f"(hi));
    return r;
}
__device__ __forceinline__ void unpack2(unsigned long long v, float& lo, float& hi) {
    asm("mov.b64 {%0, %1}, %2;" : "=f"(lo), "=f"(hi) : "l"(v));
}
__device__ __forceinline__ unsigned long long fma2(unsigned long long a,
                                                   unsigned long long b,
                                                   unsigned long long c) {
    unsigned long long d;
    asm("fma.rn.f32x2 %0, %1, %2, %3;" : "=l"(d) : "l"(a), "l"(b), "l"(c));
    return d;
}

// acc2 index for (l, m>0): pairs per l are m=1..l
__host__ __device__ constexpr int aidx(int l, int m) { return l * (l - 1) / 2 + (m - 1); }

// ---------------------------------------------------------------------------
__global__ __launch_bounds__(NTHR, 1)
void sht_main_kernel(const float* __restrict__ pos, int npts) {
    unsigned long long acc2[55];   // (l,m>0): lo = +m (real), hi = -m (imag)
    float acc0[11];                // m == 0
#pragma unroll
    for (int j = 0; j < 55; ++j) acc2[j] = 0ull;
#pragma unroll
    for (int j = 0; j < 11; ++j) acc0[j] = 0.0f;

    const int stride = gridDim.x * blockDim.x;
    for (int i = blockIdx.x * blockDim.x + threadIdx.x; i < npts; i += stride) {
        const float x  = pos[3 * i + 0];
        const float y  = pos[3 * i + 1];
        const float z0 = pos[3 * i + 2];

        const float r2 = fmaf(x, x, fmaf(y, y, z0 * z0));
        const float r  = sqrtf(r2);

        // w[k] = mask * z0 * r^k
        float w[11];
        w[0] = (r2 > 0.0f) ? z0 : 0.0f;
#pragma unroll
        for (int k = 1; k < 11; ++k) w[k] = w[k - 1] * r;

        // h[s] = r^s / s!   (h2 = broadcast pack)
        float h[11];
        unsigned long long h2[11];
        h[0] = 1.0f;
        h2[0] = pack2(1.0f, 1.0f);
        static_for<1, 11>([&](auto sc) {
            constexpr int s = decltype(sc)::value;
            const float rs = r * (float)(1.0 / (double)s);   // FMUL-imm
            h[s] = h[s - 1] * rs;
            h2[s] = pack2(h[s], h[s]);
        });

        // z1^p powers, z1 = (-x/2, -y/2)
        float zr[11], zi[11];
        zr[0] = 1.0f; zi[0] = 0.0f;
        const float ar = -0.5f * x;
        const float ai = -0.5f * y;
#pragma unroll
        for (int p = 1; p < 11; ++p) {
            zr[p] = fmaf(ar, zr[p - 1], -(ai * zi[p - 1]));
            zi[p] = fmaf(ar, zi[p - 1],  (ai * zr[p - 1]));
        }
        float sr[11], si[11];
#pragma unroll
        for (int p = 0; p < 11; ++p) { sr[p] = zr[p] * zr[p]; si[p] = zi[p] * zi[p]; }

        // 36 (p,q) pairs, p >= q, k = p+q <= 10
        static_for<0, 11>([&](auto pc) {
            constexpr int p = decltype(pc)::value;
            static_for<0, p + 1>([&](auto qc) {
                constexpr int q = decltype(qc)::value;
                if constexpr (p + q <= 10) {
                    constexpr int k = p + q;
                    constexpr int m = p - q;
                    const float D = sr[p] - si[q];
                    const float c = w[k] * cB(p, q);          // FMUL-imm
                    if constexpr (m == 0) {
                        const float Dc = D * c;
                        static_for<k, 11>([&](auto lc) {
                            constexpr int l = decltype(lc)::value;
                            acc0[l] = fmaf(Dc, h[l - k], acc0[l]);
                        });
                    } else {
                        // P carries the (-1)^q sign via operand order
                        float P;
                        if constexpr (q & 1)
                            P = fmaf(zr[p], zi[q], -(zi[p] * zr[q]));
                        else
                            P = fmaf(zi[p], zr[q], -(zr[p] * zi[q]));
                        const unsigned long long DPs = pack2(D * c, P * c);
                        static_for<k, 11>([&](auto lc) {
                            constexpr int l = decltype(lc)::value;
                            acc2[aidx(l, m)] = fma2(DPs, h2[l - k], acc2[aidx(l, m)]);
                        });
                    }
                }
            });
        });
    }

    // ---- block-level reduction: shfl within warp, smem across 8 warps ----
    __shared__ float sred[NTHR / 32][121];
    const int lane = threadIdx.x & 31;
    const int wid  = threadIdx.x >> 5;

    auto wreduce = [&](float v, int j) {
#pragma unroll
        for (int o = 16; o > 0; o >>= 1) v += __shfl_xor_sync(0xffffffffu, v, o);
        if (lane == 0) sred[wid][j] = v;
    };

    static_for<0, 11>([&](auto lc) {
        constexpr int l = decltype(lc)::value;
        wreduce(acc0[l], l * l + l);
        static_for<1, l + 1>([&](auto mc) {
            constexpr int m = decltype(mc)::value;
            float re, im;
            unpack2(acc2[aidx(l, m)], re, im);
            wreduce(re, l * l + l + m);
            wreduce(im, l * l + l - m);
        });
    });
    __syncthreads();

    if (threadIdx.x < 121) {
        float s = 0.0f;
#pragma unroll
        for (int wv = 0; wv < NTHR / 32; ++wv) s += sred[wv][threadIdx.x];
        g_part[threadIdx.x * NBLK + blockIdx.x] = s;
    }
}

// ---------------------------------------------------------------------------
__global__ void sht_reduce_kernel(float* __restrict__ out) {
    const int j = blockIdx.x;   // 0..120
    double s = 0.0;
    for (int t = threadIdx.x; t < NBLK; t += blockDim.x)
        s += (double)g_part[j * NBLK + t];
    __shared__ double sh[128];
    sh[threadIdx.x] = s;
    __syncthreads();
    for (int k = 64; k > 0; k >>= 1) {
        if (threadIdx.x < k) sh[threadIdx.x] += sh[threadIdx.x + k];
        __syncthreads();
    }
    if (threadIdx.x == 0) {
        // epilogue scale A(l,m) = sqrt((l+|m|)!(l-|m|)!) * sqrt((2l+1)/4pi) * f
        int l = 0;
        while ((l + 1) * (l + 1) <= j) ++l;
        const int M  = j - l * l - l;
        const int am = (M < 0) ? -M : M;
        double f1 = 1.0, f2 = 1.0;
        for (int t = 2; t <= l + am; ++t) f1 *= (double)t;
        for (int t = 2; t <= l - am; ++t) f2 *= (double)t;
        double scale = sqrt(f1) * sqrt(f2) *
                       sqrt((2.0 * l + 1.0) / (4.0 * 3.14159265358979323846));
        if (am) scale *= sqrt(2.0) * ((am & 1) ? -1.0 : 1.0);
        out[j] = (float)(sh[0] * scale);
    }
}

// ---------------------------------------------------------------------------
extern "C" void kernel_launch(void* const* d_in, const int* in_sizes, int n_in,
                              void* d_out, int out_size) {
    const float* pos = (const float*)d_in[0];
    const int npts = in_sizes[0] / 3;
    sht_main_kernel<<<NBLK, NTHR>>>(pos, npts);
    sht_reduce_kernel<<<121, 128>>>((float*)d_out);
}